// round 8
// baseline (speedup 1.0000x reference)
#include <cuda_runtime.h>
#include <math.h>

#define BB 2048   // batch
#define SS 64     // encode sequence length
#define HH 256    // hidden
#define NG 1024   // 4*H gate columns

// ---------------- device scratch (static, no allocations) ----------------
__device__ float g_h[2][BB * HH];     // ping-pong hidden state
__device__ float g_c[BB * HH];        // cell state (owner-exclusive per CTA tile)
__device__ float g_Wt[512 * NG];      // encode weights: k-major, gate-interleaved cols
                                      //   k<256 -> W_hh, k>=256 -> W_ih
__device__ float g_Wst[HH * NG];      // AR weights: (W_ih + W_hh)^T, gate-interleaved
__device__ float g_bias[NG];          // b_ih + b_hh, gate-interleaved

// ---------------- init: zero h0 and c ----------------
__global__ void init_kernel() {
    int idx = blockIdx.x * blockDim.x + threadIdx.x;
    const int n = BB * HH;
    for (int i = idx; i < n; i += gridDim.x * blockDim.x) {
        g_h[0][i] = 0.0f;
        g_c[i]    = 0.0f;
    }
}

// ---------------- weight prep: transpose + gate-interleave + combine ----------------
// Interleaved column layout: col' = j*4 + gate, gate in {i,f,g,o}
__global__ void prep_kernel(const float* __restrict__ W_ih,
                            const float* __restrict__ W_hh,
                            const float* __restrict__ b_ih,
                            const float* __restrict__ b_hh) {
    int idx = blockIdx.x * blockDim.x + threadIdx.x;
    const int n1 = 512 * NG;      // g_Wt
    const int n2 = HH * NG;       // g_Wst
    const int total = n1 + n2 + NG;
    for (int i = idx; i < total; i += gridDim.x * blockDim.x) {
        if (i < n1) {
            int k = i / NG, col = i - k * NG;
            int g = col & 3, j = col >> 2;
            int wrow = g * HH + j;
            g_Wt[i] = (k < HH) ? W_hh[wrow * HH + k]
                               : W_ih[wrow * HH + (k - HH)];
        } else if (i < n1 + n2) {
            int r = i - n1;
            int k = r / NG, col = r - k * NG;
            int g = col & 3, j = col >> 2;
            int wrow = g * HH + j;
            g_Wst[r] = W_ih[wrow * HH + k] + W_hh[wrow * HH + k];
        } else {
            int col = i - n1 - n2;
            int g = col & 3, j = col >> 2;
            g_bias[col] = b_ih[g * HH + j] + b_hh[g * HH + j];
        }
    }
}

__device__ __forceinline__ float sigmoidf_(float x) {
    return 1.0f / (1.0f + expf(-x));
}

// ---------------- fused LSTM step: GEMM (128x128 tile) + gates + state update ----
// K = 512: encode step (A = [h | x_t]), weights g_Wt
// K = 256: AR step     (A = h),          weights g_Wst
// outp != nullptr -> also write h_new into output column (stride ostride per row)
__global__ __launch_bounds__(256, 2)
void step_kernel(int ping, const float* __restrict__ x_t, int K,
                 float* __restrict__ outp, int ostride) {
    __shared__ float As[8][128];   // k-major activation slab
    __shared__ float Bs[8][128];   // k-major weight slab

    const float* __restrict__ h_in  = g_h[ping];
    float*       __restrict__ h_out = g_h[ping ^ 1];
    const float* __restrict__ Wt    = (K == 512) ? g_Wt : g_Wst;

    const int tid = threadIdx.x;
    const int tx  = tid & 15;        // 16 col-threads
    const int ty  = tid >> 4;        // 16 row-threads
    const int n0  = blockIdx.x * 128;
    const int m0  = blockIdx.y * 128;

    float acc[8][8];
#pragma unroll
    for (int i = 0; i < 8; i++)
#pragma unroll
        for (int j = 0; j < 8; j++) acc[i][j] = 0.0f;

    // gmem load mapping
    const int arow = tid >> 1;           // 0..127
    const int ak4  = (tid & 1) * 4;      // 0 or 4
    const int bk   = tid >> 5;           // 0..7
    const int bn4  = (tid & 31) * 4;     // 0..124

    // prologue: load first K-slab into registers
    float4 av, bv;
    {
        const int kg   = ak4;
        const int brow = m0 + arow;
        av = (kg < HH) ? *(const float4*)(h_in + brow * HH + kg)
                       : *(const float4*)(x_t + (size_t)brow * (SS * HH) + (kg - HH));
        bv = *(const float4*)(Wt + bk * NG + n0 + bn4);
    }

    for (int kb = 0; kb < K; kb += 8) {
        __syncthreads();                       // previous slab fully consumed
        As[ak4 + 0][arow] = av.x;
        As[ak4 + 1][arow] = av.y;
        As[ak4 + 2][arow] = av.z;
        As[ak4 + 3][arow] = av.w;
        *(float4*)&Bs[bk][bn4] = bv;
        __syncthreads();

        // prefetch next slab (LDG latency hidden under the 8x64-FMA block below)
        const int kn = kb + 8;
        if (kn < K) {
            const int kg   = kn + ak4;
            const int brow = m0 + arow;
            av = (kg < HH) ? *(const float4*)(h_in + brow * HH + kg)
                           : *(const float4*)(x_t + (size_t)brow * (SS * HH) + (kg - HH));
            bv = *(const float4*)(Wt + (kn + bk) * NG + n0 + bn4);
        }

#pragma unroll
        for (int k = 0; k < 8; k++) {
            float a[8], b[8];
            *(float4*)&a[0] = *(const float4*)&As[k][ty * 4];
            *(float4*)&a[4] = *(const float4*)&As[k][64 + ty * 4];
            *(float4*)&b[0] = *(const float4*)&Bs[k][tx * 4];
            *(float4*)&b[4] = *(const float4*)&Bs[k][64 + tx * 4];
#pragma unroll
            for (int ri = 0; ri < 8; ri++)
#pragma unroll
                for (int ci = 0; ci < 8; ci++)
                    acc[ri][ci] = fmaf(a[ri], b[ci], acc[ri][ci]);
        }
    }

    // ---------------- fused epilogue: gates -> new (h, c) ----------------
    const float4 bias0 = *(const float4*)&g_bias[n0 + tx * 4];
    const float4 bias1 = *(const float4*)&g_bias[n0 + 64 + tx * 4];
    const int j0 = (n0 >> 2) + tx;       // hidden index of quad 0

#pragma unroll
    for (int ri = 0; ri < 8; ri++) {
        const int row  = (ri < 4) ? (ty * 4 + ri) : (64 + ty * 4 + (ri - 4));
        const int brow = m0 + row;
#pragma unroll
        for (int q = 0; q < 2; q++) {
            const float4 bs = q ? bias1 : bias0;
            const int j = j0 + q * 16;
            const float gi = acc[ri][q * 4 + 0] + bs.x;   // input gate
            const float gf = acc[ri][q * 4 + 1] + bs.y;   // forget gate
            const float gg = acc[ri][q * 4 + 2] + bs.z;   // cell cand
            const float go = acc[ri][q * 4 + 3] + bs.w;   // output gate
            const float iv = sigmoidf_(gi);
            const float fv = sigmoidf_(gf);
            const float gv = tanhf(gg);
            const float ov = sigmoidf_(go);
            const float co = g_c[brow * HH + j];
            const float cn = fv * co + iv * gv;
            const float hn = ov * tanhf(cn);
            g_c[brow * HH + j]  = cn;
            h_out[brow * HH + j] = hn;
            if (outp) outp[(size_t)brow * ostride + j] = hn;
        }
    }
}

// ---------------- host launcher (graph-capturable, alloc-free) ----------------
extern "C" void kernel_launch(void* const* d_in, const int* in_sizes, int n_in,
                              void* d_out, int out_size) {
    const float* x0  = (const float*)d_in[0];   // [B, S, H]
    const float* Wih = (const float*)d_in[1];   // [4H, H]
    const float* Whh = (const float*)d_in[2];   // [4H, H]
    const float* bih = (const float*)d_in[3];   // [4H]
    const float* bhh = (const float*)d_in[4];   // [4H]
    float* out = (float*)d_out;                 // [B, n_steps+1, H]

    const int n_steps = out_size / (BB * HH) - 1;   // = 32 for this shape
    const int ostride = (n_steps + 1) * HH;

    init_kernel<<<264, 256>>>();
    prep_kernel<<<1536, 256>>>(Wih, Whh, bih, bhh);

    dim3 grid(8, 16);   // 8 N-tiles x 16 M-tiles = 128 CTAs
    int p = 0;

    // encode: 64 steps over x; last step's h is output column 0
    for (int t = 0; t < SS; t++) {
        float* op = (t == SS - 1) ? out : nullptr;
        step_kernel<<<grid, 256>>>(p, x0 + (size_t)t * HH, 512, op, ostride);
        p ^= 1;
    }
    // autoregressive: h feeds itself; folded weights, K=256
    for (int s = 0; s < n_steps; s++) {
        step_kernel<<<grid, 256>>>(p, x0 /*unused*/, 256,
                                   out + (size_t)(s + 1) * HH, ostride);
        p ^= 1;
    }
}

// round 10
// speedup vs baseline: 1.5486x; 1.5486x over previous
#include <cuda_runtime.h>
#include <cuda_bf16.h>
#include <cstdint>
#include <math.h>

#define BB 2048
#define SS 64
#define HH 256
#define NG 1024
#define AKW 512            // activation cols: [hi(256) | lo(256)]
#define KW_ENC 1536        // 3 * 512
#define KW_AR  768         // 3 * 256

// ---------------- static device scratch (no allocations) ----------------
__device__ __align__(128) __nv_bfloat16 g_hbuf[2][BB * AKW];          // ping-pong h (hi|lo)
__device__ __align__(128) float         g_c[BB * HH];                 // cell state fp32
__device__ __align__(128) __nv_bfloat16 g_Wb[NG * KW_ENC];            // [n][k] enc weights
__device__ __align__(128) __nv_bfloat16 g_Wsb[NG * KW_AR];            // [n][k] AR weights
__device__ __align__(128) __nv_bfloat16 g_xs[(size_t)SS * BB * AKW];  // x split per t
__device__ __align__(16)  float         g_bias[NG];

// ---------------- smem: stride-144B rows (64 bf16 + 8 pad) ----------------
#define ROWB   144
#define TILEB  (128 * ROWB)      // 18432 B per operand buffer
#define SM_A0  0
#define SM_B0  TILEB
#define SM_A1  (2 * TILEB)
#define SM_B1  (3 * TILEB)
#define SM_TOT (4 * TILEB)       // 73728 B dynamic smem

__device__ __forceinline__ uint32_t smem_u32(const void* p) {
    uint32_t r;
    asm("{ .reg .u64 t; cvta.to.shared.u64 t, %1; cvt.u32.u64 %0, t; }" : "=r"(r) : "l"(p));
    return r;
}

#define LDSM4(r0, r1, r2, r3, addr)                                         \
    asm volatile("ldmatrix.sync.aligned.m8n8.x4.shared.b16 {%0,%1,%2,%3}, [%4];" \
                 : "=r"(r0), "=r"(r1), "=r"(r2), "=r"(r3) : "r"(addr))

#define MMA16816(d, a, b)                                                   \
    asm volatile("mma.sync.aligned.m16n8k16.row.col.f32.bf16.bf16.f32 "     \
                 "{%0,%1,%2,%3}, {%4,%5,%6,%7}, {%8,%9}, {%0,%1,%2,%3};"    \
                 : "+f"((d)[0]), "+f"((d)[1]), "+f"((d)[2]), "+f"((d)[3])   \
                 : "r"((a)[0]), "r"((a)[1]), "r"((a)[2]), "r"((a)[3]),      \
                   "r"((b)[0]), "r"((b)[1]))

// ---------------- init ----------------
__global__ void init_k() {
    int idx = blockIdx.x * blockDim.x + threadIdx.x;
    const int stride = gridDim.x * blockDim.x;
    for (int i = idx; i < BB * AKW; i += stride) g_hbuf[0][i] = __float2bfloat16(0.0f);
    for (int i = idx; i < BB * HH; i += stride) g_c[i] = 0.0f;
}

// ---------------- weight prep: gate-interleave + hi/lo split + K-concat ----------------
// enc K segs: [Whh_hi, Wih_hi, Whh_hi, Wih_hi, Whh_lo, Wih_lo] (256 each)
// AR  K segs: [Ws_hi, Ws_hi, Ws_lo]
__global__ void prep_w(const float* __restrict__ Wih, const float* __restrict__ Whh,
                       const float* __restrict__ bih, const float* __restrict__ bhh) {
    int idx = blockIdx.x * blockDim.x + threadIdx.x;
    const int stride = gridDim.x * blockDim.x;
    const int n1 = NG * KW_ENC;
    const int n2 = NG * KW_AR;
    const int total = n1 + n2 + NG;
    for (int i = idx; i < total; i += stride) {
        if (i < n1) {
            int n = i / KW_ENC, kk = i - n * KW_ENC;
            int g = n & 3, j = n >> 2, wrow = g * HH + j;
            int seg = kk >> 8, k = kk & 255;
            float v; bool lo;
            if (seg == 0 || seg == 2)      { v = Whh[wrow * HH + k]; lo = false; }
            else if (seg == 1 || seg == 3) { v = Wih[wrow * HH + k]; lo = false; }
            else if (seg == 4)             { v = Whh[wrow * HH + k]; lo = true;  }
            else                           { v = Wih[wrow * HH + k]; lo = true;  }
            __nv_bfloat16 hi = __float2bfloat16(v);
            g_Wb[i] = lo ? __float2bfloat16(v - __bfloat162float(hi)) : hi;
        } else if (i < n1 + n2) {
            int r = i - n1;
            int n = r / KW_AR, kk = r - n * KW_AR;
            int g = n & 3, j = n >> 2, wrow = g * HH + j;
            int seg = kk >> 8, k = kk & 255;
            float v = Wih[wrow * HH + k] + Whh[wrow * HH + k];
            __nv_bfloat16 hi = __float2bfloat16(v);
            g_Wsb[r] = (seg == 2) ? __float2bfloat16(v - __bfloat162float(hi)) : hi;
        } else {
            int n = i - n1 - n2;
            int g = n & 3, j = n >> 2;
            g_bias[n] = bih[g * HH + j] + bhh[g * HH + j];
        }
    }
}

// ---------------- x split: [B,S,H] fp32 -> per-t [B, hi|lo] bf16 ----------------
__global__ void prep_x(const float* __restrict__ x0) {
    size_t idx = (size_t)blockIdx.x * blockDim.x + threadIdx.x;
    const size_t stride = (size_t)gridDim.x * blockDim.x;
    const size_t total = (size_t)SS * BB * HH;
    for (size_t i = idx; i < total; i += stride) {
        size_t tm = i / HH;
        int k = (int)(i - tm * HH);
        int m = (int)(tm % BB);
        int t = (int)(tm / BB);
        float v = x0[((size_t)m * SS + t) * HH + k];
        __nv_bfloat16 hi = __float2bfloat16(v);
        __nv_bfloat16 lo = __float2bfloat16(v - __bfloat162float(hi));
        size_t base = ((size_t)t * BB + m) * AKW;
        g_xs[base + k] = hi;
        g_xs[base + 256 + k] = lo;
    }
}

// ---------------- K=64 chunk loaders ----------------
__device__ __forceinline__ void ldg_chunk(int kc, int m0, int n0,
                                          const __nv_bfloat16* __restrict__ hin,
                                          const __nv_bfloat16* __restrict__ xt, int enc,
                                          const __nv_bfloat16* __restrict__ W, int wstride,
                                          int tid, uint4* ra, uint4* rb) {
    const int seg = kc >> 2, off = (kc & 3) * 64;
    const __nv_bfloat16* asrc; int acol;
    if (enc) {
        switch (seg) {   // A segs: [h_hi, x_hi, h_lo, x_lo, h_hi, x_hi]
            case 0: case 4: asrc = hin; acol = off; break;
            case 1: case 5: asrc = xt;  acol = off; break;
            case 2:         asrc = hin; acol = 256 + off; break;
            default:        asrc = xt;  acol = 256 + off; break;
        }
    } else {             // A segs: [h_hi, h_lo, h_hi]
        asrc = hin; acol = (seg == 1 ? 256 : 0) + off;
    }
    const __nv_bfloat16* bsrc = W + (size_t)kc * 64;
#pragma unroll
    for (int j = 0; j < 4; j++) {
        int idx = tid + j * 256;
        int row = idx >> 3, c8 = idx & 7;
        ra[j] = *(const uint4*)(asrc + (size_t)(m0 + row) * AKW + acol + c8 * 8);
        rb[j] = *(const uint4*)(bsrc + (size_t)(n0 + row) * wstride + c8 * 8);
    }
}

__device__ __forceinline__ void sts_chunk(char* smem, int bufA, int bufB, int tid,
                                          const uint4* ra, const uint4* rb) {
#pragma unroll
    for (int j = 0; j < 4; j++) {
        int idx = tid + j * 256;
        int row = idx >> 3, c8 = idx & 7;
        uint32_t off = (uint32_t)(row * ROWB + c8 * 16);
        *(uint4*)(smem + bufA + off) = ra[j];
        *(uint4*)(smem + bufB + off) = rb[j];
    }
}

// ---------------- fused LSTM step on mma.sync bf16 ----------------
__global__ __launch_bounds__(256)
void step_mma(int ping, int t, float* __restrict__ outp, int ostride) {
    extern __shared__ char smem[];
    const int tid = threadIdx.x;
    const int wid = tid >> 5, lane = tid & 31;
    const int warp_m = wid >> 2, warp_n = wid & 3;   // 2 x 4 warp grid
    const int n0 = blockIdx.x * 128, m0 = blockIdx.y * 128;
    const int enc = (t >= 0);
    const int NCH = enc ? (KW_ENC / 64) : (KW_AR / 64);   // 24 or 12
    const __nv_bfloat16* __restrict__ hin = g_hbuf[ping];
    __nv_bfloat16* __restrict__ hout = g_hbuf[ping ^ 1];
    const __nv_bfloat16* __restrict__ W = enc ? g_Wb : g_Wsb;
    const int wstride = enc ? KW_ENC : KW_AR;
    const __nv_bfloat16* __restrict__ xt =
        enc ? (g_xs + (size_t)t * BB * AKW) : (const __nv_bfloat16*)0;

    const uint32_t sbase = smem_u32(smem);

    // ldmatrix per-thread base offsets (within a 128x64 stride-144 tile)
    // A: mat = lane>>3: bit0 -> +8 rows, bit1 -> +8 k
    const uint32_t a_off = (uint32_t)((warp_m * 64 + (lane & 7) + ((lane >> 3) & 1) * 8) * ROWB
                                      + ((lane >> 4) & 1) * 16);
    // B: bit0 of mat -> +8 k, bit1 -> +8 n
    const uint32_t b_off = (uint32_t)((warp_n * 32 + (lane & 7) + ((lane >> 4) & 1) * 8) * ROWB
                                      + ((lane >> 3) & 1) * 16);

    float acc[4][4][4];
#pragma unroll
    for (int i = 0; i < 4; i++)
#pragma unroll
        for (int j = 0; j < 4; j++)
#pragma unroll
            for (int r = 0; r < 4; r++) acc[i][j][r] = 0.0f;

    uint4 ra[4], rb[4];
    ldg_chunk(0, m0, n0, hin, xt, enc, W, wstride, tid, ra, rb);
    sts_chunk(smem, SM_A0, SM_B0, tid, ra, rb);
    __syncthreads();
    if (NCH > 1) ldg_chunk(1, m0, n0, hin, xt, enc, W, wstride, tid, ra, rb);

    for (int i = 0; i < NCH; i++) {
        const uint32_t Ab = sbase + ((i & 1) ? SM_A1 : SM_A0);
        const uint32_t Bb = sbase + ((i & 1) ? SM_B1 : SM_B0);
#pragma unroll
        for (int ks = 0; ks < 4; ks++) {
            uint32_t af[4][4], bf[4][2];
#pragma unroll
            for (int mt = 0; mt < 4; mt++)
                LDSM4(af[mt][0], af[mt][1], af[mt][2], af[mt][3],
                      Ab + a_off + mt * (16 * ROWB) + ks * 32);
#pragma unroll
            for (int p = 0; p < 2; p++) {
                uint32_t r0, r1, r2, r3;
                LDSM4(r0, r1, r2, r3, Bb + b_off + p * (16 * ROWB) + ks * 32);
                bf[2 * p][0] = r0; bf[2 * p][1] = r1;
                bf[2 * p + 1][0] = r2; bf[2 * p + 1][1] = r3;
            }
#pragma unroll
            for (int mt = 0; mt < 4; mt++)
#pragma unroll
                for (int nt = 0; nt < 4; nt++)
                    MMA16816(acc[mt][nt], af[mt], bf[nt]);
        }
        if (i + 1 < NCH) {
            __syncthreads();
            sts_chunk(smem, (i & 1) ? SM_A0 : SM_A1, (i & 1) ? SM_B0 : SM_B1, tid, ra, rb);
            __syncthreads();
            if (i + 2 < NCH) ldg_chunk(i + 2, m0, n0, hin, xt, enc, W, wstride, tid, ra, rb);
        }
    }

    // ---------------- fused epilogue: quad gather via shfl -> gates -> (h, c) ----------
    const int c = lane & 3, g = lane >> 2;
#pragma unroll
    for (int mt = 0; mt < 4; mt++)
#pragma unroll
        for (int nt = 0; nt < 4; nt++) {
            float q0 = acc[mt][nt][0], q1 = acc[mt][nt][1];
            float q2 = acc[mt][nt][2], q3 = acc[mt][nt][3];
            float p0 = __shfl_xor_sync(0xffffffffu, q0, 1);
            float p1 = __shfl_xor_sync(0xffffffffu, q1, 1);
            float p2 = __shfl_xor_sync(0xffffffffu, q2, 1);
            float p3 = __shfl_xor_sync(0xffffffffu, q3, 1);
            float gi, gf, gg, go;
            int row;
            if ((c & 1) == 0) { gi = q0; gf = q1; gg = p0; go = p1; row = g; }
            else              { gi = p2; gf = p3; gg = q2; go = q3; row = g + 8; }
            const int nq = n0 + warp_n * 32 + nt * 8 + (c >> 1) * 4;
            const int brow = m0 + warp_m * 64 + mt * 16 + row;
            const float4 bs = *(const float4*)&g_bias[nq];
            gi += bs.x; gf += bs.y; gg += bs.z; go += bs.w;
            const float iv = 1.0f / (1.0f + __expf(-gi));
            const float fv = 1.0f / (1.0f + __expf(-gf));
            const float gv = tanhf(gg);
            const float ov = 1.0f / (1.0f + __expf(-go));
            const int j = nq >> 2;
            const int ci = brow * HH + j;
            const float cn = fv * g_c[ci] + iv * gv;
            const float hn = ov * tanhf(cn);
            g_c[ci] = cn;
            __nv_bfloat16 hi = __float2bfloat16(hn);
            __nv_bfloat16 lo = __float2bfloat16(hn - __bfloat162float(hi));
            hout[(size_t)brow * AKW + j] = hi;
            hout[(size_t)brow * AKW + 256 + j] = lo;
            if (outp) outp[(size_t)brow * ostride + j] = hn;
        }
}

// ---------------- host launcher (graph-capturable, alloc-free) ----------------
extern "C" void kernel_launch(void* const* d_in, const int* in_sizes, int n_in,
                              void* d_out, int out_size) {
    const float* x0  = (const float*)d_in[0];
    const float* Wih = (const float*)d_in[1];
    const float* Whh = (const float*)d_in[2];
    const float* bih = (const float*)d_in[3];
    const float* bhh = (const float*)d_in[4];
    float* out = (float*)d_out;

    const int n_steps = out_size / (BB * HH) - 1;
    const int ostride = (n_steps + 1) * HH;

    cudaFuncSetAttribute(step_mma, cudaFuncAttributeMaxDynamicSharedMemorySize, SM_TOT);

    init_k<<<512, 256>>>();
    prep_w<<<2048, 256>>>(Wih, Whh, bih, bhh);
    prep_x<<<4096, 256>>>(x0);

    dim3 grid(8, 16);
    int p = 0;
    for (int t = 0; t < SS; t++) {
        float* op = (t == SS - 1) ? out : (float*)0;
        step_mma<<<grid, 256, SM_TOT>>>(p, t, op, ostride);
        p ^= 1;
    }
    for (int s = 0; s < n_steps; s++) {
        step_mma<<<grid, 256, SM_TOT>>>(p, -1, out + (size_t)(s + 1) * HH, ostride);
        p ^= 1;
    }
}

// round 11
// speedup vs baseline: 1.6210x; 1.0467x over previous
#include <cuda_runtime.h>
#include <cuda_bf16.h>
#include <cstdint>
#include <math.h>

#define BB 2048
#define SS 64
#define HH 256
#define NG 1024
#define AKW 512            // activation cols: [hi(256) | lo(256)]
#define KW_ENC 1536        // 3 * 512
#define KW_AR  768         // 3 * 256

// ---------------- static device scratch (no allocations) ----------------
__device__ __align__(128) __nv_bfloat16 g_hbuf[2][BB * AKW];          // ping-pong h (hi|lo)
__device__ __align__(128) float         g_c[BB * HH];                 // cell state fp32
__device__ __align__(128) __nv_bfloat16 g_Wb[NG * KW_ENC];            // [n][k] enc weights
__device__ __align__(128) __nv_bfloat16 g_Wsb[NG * KW_AR];            // [n][k] AR weights
__device__ __align__(128) __nv_bfloat16 g_xs[(size_t)SS * BB * AKW];  // x split per t
__device__ __align__(16)  float         g_bias[NG];

// ---------------- smem: 4-stage cp.async pipeline, stride-144B rows ----------------
#define ROWB    144
#define TILEB   (128 * ROWB)          // 18432 B per operand
#define STAGEB  (2 * TILEB)           // A then B
#define STAGES  4
#define SM_TOT  (STAGES * STAGEB)     // 147456 B

__device__ __forceinline__ uint32_t smem_u32(const void* p) {
    uint32_t r;
    asm("{ .reg .u64 t; cvta.to.shared.u64 t, %1; cvt.u32.u64 %0, t; }" : "=r"(r) : "l"(p));
    return r;
}

#define CPASYNC16(saddr, gptr) \
    asm volatile("cp.async.cg.shared.global [%0], [%1], 16;" :: "r"(saddr), "l"(gptr))
#define CP_COMMIT() asm volatile("cp.async.commit_group;" ::: "memory")
#define CP_WAIT2()  asm volatile("cp.async.wait_group 2;" ::: "memory")

#define LDSM4(r0, r1, r2, r3, addr)                                              \
    asm volatile("ldmatrix.sync.aligned.m8n8.x4.shared.b16 {%0,%1,%2,%3}, [%4];" \
                 : "=r"(r0), "=r"(r1), "=r"(r2), "=r"(r3) : "r"(addr))

#define MMA16816(d, a, b)                                                   \
    asm volatile("mma.sync.aligned.m16n8k16.row.col.f32.bf16.bf16.f32 "     \
                 "{%0,%1,%2,%3}, {%4,%5,%6,%7}, {%8,%9}, {%0,%1,%2,%3};"    \
                 : "+f"((d)[0]), "+f"((d)[1]), "+f"((d)[2]), "+f"((d)[3])   \
                 : "r"((a)[0]), "r"((a)[1]), "r"((a)[2]), "r"((a)[3]),      \
                   "r"((b)[0]), "r"((b)[1]))

// ---------------- init ----------------
__global__ void init_k() {
    int idx = blockIdx.x * blockDim.x + threadIdx.x;
    const int stride = gridDim.x * blockDim.x;
    for (int i = idx; i < BB * AKW; i += stride) g_hbuf[0][i] = __float2bfloat16(0.0f);
    for (int i = idx; i < BB * HH; i += stride) g_c[i] = 0.0f;
}

// ---------------- weight prep: gate-interleave + hi/lo split + K-concat ----------------
// enc K segs: [Whh_hi, Wih_hi, Whh_hi, Wih_hi, Whh_lo, Wih_lo] (256 each)
// AR  K segs: [Ws_hi, Ws_hi, Ws_lo]
__global__ void prep_w(const float* __restrict__ Wih, const float* __restrict__ Whh,
                       const float* __restrict__ bih, const float* __restrict__ bhh) {
    int idx = blockIdx.x * blockDim.x + threadIdx.x;
    const int stride = gridDim.x * blockDim.x;
    const int n1 = NG * KW_ENC;
    const int n2 = NG * KW_AR;
    const int total = n1 + n2 + NG;
    for (int i = idx; i < total; i += stride) {
        if (i < n1) {
            int n = i / KW_ENC, kk = i - n * KW_ENC;
            int g = n & 3, j = n >> 2, wrow = g * HH + j;
            int seg = kk >> 8, k = kk & 255;
            float v; bool lo;
            if (seg == 0 || seg == 2)      { v = Whh[wrow * HH + k]; lo = false; }
            else if (seg == 1 || seg == 3) { v = Wih[wrow * HH + k]; lo = false; }
            else if (seg == 4)             { v = Whh[wrow * HH + k]; lo = true;  }
            else                           { v = Wih[wrow * HH + k]; lo = true;  }
            __nv_bfloat16 hi = __float2bfloat16(v);
            g_Wb[i] = lo ? __float2bfloat16(v - __bfloat162float(hi)) : hi;
        } else if (i < n1 + n2) {
            int r = i - n1;
            int n = r / KW_AR, kk = r - n * KW_AR;
            int g = n & 3, j = n >> 2, wrow = g * HH + j;
            int seg = kk >> 8, k = kk & 255;
            float v = Wih[wrow * HH + k] + Whh[wrow * HH + k];
            __nv_bfloat16 hi = __float2bfloat16(v);
            g_Wsb[r] = (seg == 2) ? __float2bfloat16(v - __bfloat162float(hi)) : hi;
        } else {
            int n = i - n1 - n2;
            int g = n & 3, j = n >> 2;
            g_bias[n] = bih[g * HH + j] + bhh[g * HH + j];
        }
    }
}

// ---------------- x split: [B,S,H] fp32 -> per-t [B, hi|lo] bf16 ----------------
__global__ void prep_x(const float* __restrict__ x0) {
    size_t idx = (size_t)blockIdx.x * blockDim.x + threadIdx.x;
    const size_t stride = (size_t)gridDim.x * blockDim.x;
    const size_t total = (size_t)SS * BB * HH;
    for (size_t i = idx; i < total; i += stride) {
        size_t tm = i / HH;
        int k = (int)(i - tm * HH);
        int m = (int)(tm % BB);
        int t = (int)(tm / BB);
        float v = x0[((size_t)m * SS + t) * HH + k];
        __nv_bfloat16 hi = __float2bfloat16(v);
        __nv_bfloat16 lo = __float2bfloat16(v - __bfloat162float(hi));
        size_t base = ((size_t)t * BB + m) * AKW;
        g_xs[base + k] = hi;
        g_xs[base + 256 + k] = lo;
    }
}

// ---------------- async K=64 chunk issue (gmem -> smem stage) ----------------
__device__ __forceinline__ void issue_chunk(int kc, int stage, uint32_t sbase,
                                            int m0, int n0,
                                            const __nv_bfloat16* __restrict__ hin,
                                            const __nv_bfloat16* __restrict__ xt, int enc,
                                            const __nv_bfloat16* __restrict__ W, int wstride,
                                            int tid) {
    const int seg = kc >> 2, off = (kc & 3) * 64;
    const __nv_bfloat16* asrc; int acol;
    if (enc) {
        switch (seg) {   // A segs: [h_hi, x_hi, h_lo, x_lo, h_hi, x_hi]
            case 0: case 4: asrc = hin; acol = off; break;
            case 1: case 5: asrc = xt;  acol = off; break;
            case 2:         asrc = hin; acol = 256 + off; break;
            default:        asrc = xt;  acol = 256 + off; break;
        }
    } else {             // A segs: [h_hi, h_lo, h_hi]
        asrc = hin; acol = (seg == 1 ? 256 : 0) + off;
    }
    const __nv_bfloat16* bsrc = W + (size_t)kc * 64;
    const uint32_t Ab = sbase + stage * STAGEB;
    const uint32_t Bb = Ab + TILEB;
#pragma unroll
    for (int j = 0; j < 4; j++) {
        int idx = tid + j * 256;
        int row = idx >> 3, c8 = idx & 7;
        uint32_t soff = (uint32_t)(row * ROWB + c8 * 16);
        CPASYNC16(Ab + soff, (const void*)(asrc + (size_t)(m0 + row) * AKW + acol + c8 * 8));
        CPASYNC16(Bb + soff, (const void*)(bsrc + (size_t)(n0 + row) * wstride + c8 * 8));
    }
}

// ---------------- fragment loads for one k16 slice ----------------
__device__ __forceinline__ void load_frags(int ks, uint32_t Ab, uint32_t Bb,
                                           uint32_t a_off, uint32_t b_off,
                                           uint32_t af[4][4], uint32_t bf[4][2]) {
#pragma unroll
    for (int mt = 0; mt < 4; mt++)
        LDSM4(af[mt][0], af[mt][1], af[mt][2], af[mt][3],
              Ab + a_off + mt * (16 * ROWB) + ks * 32);
#pragma unroll
    for (int p = 0; p < 2; p++) {
        uint32_t r0, r1, r2, r3;
        LDSM4(r0, r1, r2, r3, Bb + b_off + p * (16 * ROWB) + ks * 32);
        bf[2 * p][0] = r0; bf[2 * p][1] = r1;
        bf[2 * p + 1][0] = r2; bf[2 * p + 1][1] = r3;
    }
}

// ---------------- fused LSTM step on mma.sync bf16, cp.async 4-stage ----------------
__global__ __launch_bounds__(256)
void step_mma(int ping, int t, float* __restrict__ outp, int ostride) {
    extern __shared__ char smem[];
    const int tid = threadIdx.x;
    const int wid = tid >> 5, lane = tid & 31;
    const int warp_m = wid >> 2, warp_n = wid & 3;   // 2 x 4 warp grid
    const int n0 = blockIdx.x * 128, m0 = blockIdx.y * 128;
    const int enc = (t >= 0);
    const int NCH = enc ? (KW_ENC / 64) : (KW_AR / 64);   // 24 or 12
    const __nv_bfloat16* __restrict__ hin = g_hbuf[ping];
    __nv_bfloat16* __restrict__ hout = g_hbuf[ping ^ 1];
    const __nv_bfloat16* __restrict__ W = enc ? g_Wb : g_Wsb;
    const int wstride = enc ? KW_ENC : KW_AR;
    const __nv_bfloat16* __restrict__ xt =
        enc ? (g_xs + (size_t)t * BB * AKW) : (const __nv_bfloat16*)0;

    const uint32_t sbase = smem_u32(smem);

    // ldmatrix per-thread base offsets (within a 128x64 stride-144 tile)
    const uint32_t a_off = (uint32_t)((warp_m * 64 + (lane & 7) + ((lane >> 3) & 1) * 8) * ROWB
                                      + ((lane >> 4) & 1) * 16);
    const uint32_t b_off = (uint32_t)((warp_n * 32 + (lane & 7) + ((lane >> 4) & 1) * 8) * ROWB
                                      + ((lane >> 3) & 1) * 16);

    float acc[4][4][4];
#pragma unroll
    for (int i = 0; i < 4; i++)
#pragma unroll
        for (int j = 0; j < 4; j++)
#pragma unroll
            for (int r = 0; r < 4; r++) acc[i][j][r] = 0.0f;

    // prologue: issue chunks 0 .. STAGES-2
#pragma unroll
    for (int s = 0; s < STAGES - 1; s++) {
        issue_chunk(s, s, sbase, m0, n0, hin, xt, enc, W, wstride, tid);
        CP_COMMIT();
    }

    for (int i = 0; i < NCH; i++) {
        CP_WAIT2();            // chunk i (and i+1) landed
        __syncthreads();       // all warps done with chunk i-1's stage -> safe to reuse

        const int nx = i + STAGES - 1;
        if (nx < NCH)
            issue_chunk(nx, nx & (STAGES - 1), sbase, m0, n0, hin, xt, enc, W, wstride, tid);
        CP_COMMIT();           // commit every iter (possibly empty) to keep group count fixed

        const uint32_t Ab = sbase + (i & (STAGES - 1)) * STAGEB;
        const uint32_t Bb = Ab + TILEB;

        uint32_t af[2][4][4], bf[2][4][2];
        load_frags(0, Ab, Bb, a_off, b_off, af[0], bf[0]);
#pragma unroll
        for (int ks = 0; ks < 4; ks++) {
            const int cur = ks & 1;
            if (ks < 3)
                load_frags(ks + 1, Ab, Bb, a_off, b_off, af[cur ^ 1], bf[cur ^ 1]);
#pragma unroll
            for (int mt = 0; mt < 4; mt++)
#pragma unroll
                for (int nt = 0; nt < 4; nt++)
                    MMA16816(acc[mt][nt], af[cur][mt], bf[cur][nt]);
        }
    }

    // ---------------- fused epilogue: quad gather via shfl -> gates -> (h, c) ----------
    const int c = lane & 3, g = lane >> 2;
#pragma unroll
    for (int mt = 0; mt < 4; mt++)
#pragma unroll
        for (int nt = 0; nt < 4; nt++) {
            float q0 = acc[mt][nt][0], q1 = acc[mt][nt][1];
            float q2 = acc[mt][nt][2], q3 = acc[mt][nt][3];
            float p0 = __shfl_xor_sync(0xffffffffu, q0, 1);
            float p1 = __shfl_xor_sync(0xffffffffu, q1, 1);
            float p2 = __shfl_xor_sync(0xffffffffu, q2, 1);
            float p3 = __shfl_xor_sync(0xffffffffu, q3, 1);
            float gi, gf, gg, go;
            int row;
            if ((c & 1) == 0) { gi = q0; gf = q1; gg = p0; go = p1; row = g; }
            else              { gi = p2; gf = p3; gg = q2; go = q3; row = g + 8; }
            const int nq = n0 + warp_n * 32 + nt * 8 + (c >> 1) * 4;
            const int brow = m0 + warp_m * 64 + mt * 16 + row;
            const float4 bs = *(const float4*)&g_bias[nq];
            gi += bs.x; gf += bs.y; gg += bs.z; go += bs.w;
            const float iv = 1.0f / (1.0f + __expf(-gi));
            const float fv = 1.0f / (1.0f + __expf(-gf));
            const float gv = tanhf(gg);
            const float ov = 1.0f / (1.0f + __expf(-go));
            const int j = nq >> 2;
            const int ci = brow * HH + j;
            const float cn = fv * g_c[ci] + iv * gv;
            const float hn = ov * tanhf(cn);
            g_c[ci] = cn;
            __nv_bfloat16 hi = __float2bfloat16(hn);
            __nv_bfloat16 lo = __float2bfloat16(hn - __bfloat162float(hi));
            hout[(size_t)brow * AKW + j] = hi;
            hout[(size_t)brow * AKW + 256 + j] = lo;
            if (outp) outp[(size_t)brow * ostride + j] = hn;
        }
}

// ---------------- host launcher (graph-capturable, alloc-free) ----------------
extern "C" void kernel_launch(void* const* d_in, const int* in_sizes, int n_in,
                              void* d_out, int out_size) {
    const float* x0  = (const float*)d_in[0];
    const float* Wih = (const float*)d_in[1];
    const float* Whh = (const float*)d_in[2];
    const float* bih = (const float*)d_in[3];
    const float* bhh = (const float*)d_in[4];
    float* out = (float*)d_out;

    const int n_steps = out_size / (BB * HH) - 1;
    const int ostride = (n_steps + 1) * HH;

    cudaFuncSetAttribute(step_mma, cudaFuncAttributeMaxDynamicSharedMemorySize, SM_TOT);

    init_k<<<512, 256>>>();
    prep_w<<<2048, 256>>>(Wih, Whh, bih, bhh);
    prep_x<<<4096, 256>>>(x0);

    dim3 grid(8, 16);
    int p = 0;
    for (int t = 0; t < SS; t++) {
        float* op = (t == SS - 1) ? out : (float*)0;
        step_mma<<<grid, 256, SM_TOT>>>(p, t, op, ostride);
        p ^= 1;
    }
    for (int s = 0; s < n_steps; s++) {
        step_mma<<<grid, 256, SM_TOT>>>(p, -1, out + (size_t)(s + 1) * HH, ostride);
        p ^= 1;
    }
}

// round 12
// speedup vs baseline: 2.0836x; 1.2854x over previous
#include <cuda_runtime.h>
#include <cuda_fp16.h>
#include <cstdint>
#include <math.h>

#define BB 2048
#define SS 64
#define HH 256
#define NG 1024
#define AKW 512            // activation cols: [hi(256) | lo(256)]
#define KW_ENC 1024        // 2 * 512  (fp16 2-term split)
#define KW_AR  512         // 2 * 256
#define TM 64              // CTA tile M
#define TN 128             // CTA tile N

// ---------------- static device scratch (no allocations) ----------------
__device__ __align__(128) __half g_hbuf[2][BB * AKW];           // ping-pong h (hi|lo)
__device__ __align__(128) float  g_c[BB * HH];                  // cell state fp32
__device__ __align__(128) __half g_Wb[NG * KW_ENC];             // [n][k] enc weights
__device__ __align__(128) __half g_Wsb[NG * KW_AR];             // [n][k] AR weights
__device__ __align__(128) __half g_xs[(size_t)SS * BB * AKW];   // x split per t
__device__ __align__(16)  float  g_bias[NG];

// ---------------- smem: 3-stage cp.async pipeline, stride-144B rows ----------------
#define ROWB    144
#define A_TILEB (TM * ROWB)           // 9216
#define B_TILEB (TN * ROWB)           // 18432
#define STAGEB  (A_TILEB + B_TILEB)   // 27648
#define STAGES  3
#define SM_TOT  (STAGES * STAGEB)     // 82944 B -> 2 CTAs/SM fit in 228KB

__device__ __forceinline__ uint32_t smem_u32(const void* p) {
    uint32_t r;
    asm("{ .reg .u64 t; cvta.to.shared.u64 t, %1; cvt.u32.u64 %0, t; }" : "=r"(r) : "l"(p));
    return r;
}

#define CPASYNC16(saddr, gptr) \
    asm volatile("cp.async.cg.shared.global [%0], [%1], 16;" :: "r"(saddr), "l"(gptr))
#define CP_COMMIT() asm volatile("cp.async.commit_group;" ::: "memory")
#define CP_WAIT1()  asm volatile("cp.async.wait_group 1;" ::: "memory")

#define LDSM4(r0, r1, r2, r3, addr)                                              \
    asm volatile("ldmatrix.sync.aligned.m8n8.x4.shared.b16 {%0,%1,%2,%3}, [%4];" \
                 : "=r"(r0), "=r"(r1), "=r"(r2), "=r"(r3) : "r"(addr))

#define MMA16816(d, a, b)                                                   \
    asm volatile("mma.sync.aligned.m16n8k16.row.col.f32.f16.f16.f32 "       \
                 "{%0,%1,%2,%3}, {%4,%5,%6,%7}, {%8,%9}, {%0,%1,%2,%3};"    \
                 : "+f"((d)[0]), "+f"((d)[1]), "+f"((d)[2]), "+f"((d)[3])   \
                 : "r"((a)[0]), "r"((a)[1]), "r"((a)[2]), "r"((a)[3]),      \
                   "r"((b)[0]), "r"((b)[1]))

// ---------------- init ----------------
__global__ void init_k() {
    int idx = blockIdx.x * blockDim.x + threadIdx.x;
    const int stride = gridDim.x * blockDim.x;
    for (int i = idx; i < BB * AKW; i += stride) g_hbuf[0][i] = __float2half(0.0f);
    for (int i = idx; i < BB * HH; i += stride) g_c[i] = 0.0f;
}

// ---------------- weight prep: gate-interleave + K-concat (fp16, duplicated) ------
// enc K segs (256 each): [Whh, Wih, Whh, Wih]  (same W multiplies h_hi and h_lo)
// AR  K segs:            [Ws, Ws]              (Ws = Wih + Whh)
__global__ void prep_w(const float* __restrict__ Wih, const float* __restrict__ Whh,
                       const float* __restrict__ bih, const float* __restrict__ bhh) {
    int idx = blockIdx.x * blockDim.x + threadIdx.x;
    const int stride = gridDim.x * blockDim.x;
    const int n1 = NG * KW_ENC;
    const int n2 = NG * KW_AR;
    const int total = n1 + n2 + NG;
    for (int i = idx; i < total; i += stride) {
        if (i < n1) {
            int n = i / KW_ENC, kk = i - n * KW_ENC;
            int g = n & 3, j = n >> 2, wrow = g * HH + j;
            int seg = kk >> 8, k = kk & 255;
            float v = (seg & 1) ? Wih[wrow * HH + k] : Whh[wrow * HH + k];
            g_Wb[i] = __float2half(v);
        } else if (i < n1 + n2) {
            int r = i - n1;
            int n = r / KW_AR, kk = r - n * KW_AR;
            int g = n & 3, j = n >> 2, wrow = g * HH + j;
            int k = kk & 255;
            g_Wsb[r] = __float2half(Wih[wrow * HH + k] + Whh[wrow * HH + k]);
        } else {
            int n = i - n1 - n2;
            int g = n & 3, j = n >> 2;
            g_bias[n] = bih[g * HH + j] + bhh[g * HH + j];
        }
    }
}

// ---------------- x split: [B,S,H] fp32 -> per-t [B, hi|lo] fp16 ----------------
__global__ void prep_x(const float* __restrict__ x0) {
    size_t idx = (size_t)blockIdx.x * blockDim.x + threadIdx.x;
    const size_t stride = (size_t)gridDim.x * blockDim.x;
    const size_t total = (size_t)SS * BB * HH;
    for (size_t i = idx; i < total; i += stride) {
        size_t tm = i / HH;
        int k = (int)(i - tm * HH);
        int m = (int)(tm % BB);
        int t = (int)(tm / BB);
        float v = x0[((size_t)m * SS + t) * HH + k];
        __half hi = __float2half(v);
        __half lo = __float2half(v - __half2float(hi));
        size_t base = ((size_t)t * BB + m) * AKW;
        g_xs[base + k] = hi;
        g_xs[base + 256 + k] = lo;
    }
}

// ---------------- async K=64 chunk issue (gmem -> smem stage) ----------------
// A tile 64x64 fp16, B tile 128x64 fp16 per chunk.
__device__ __forceinline__ void issue_chunk(int kc, int stage, uint32_t sbase,
                                            int m0, int n0,
                                            const __half* __restrict__ hin,
                                            const __half* __restrict__ xt, int enc,
                                            const __half* __restrict__ W, int wstride,
                                            int tid) {
    const int seg = kc >> 2, off = (kc & 3) * 64;
    const __half* asrc; int acol;
    if (enc) {   // A segs: [h_hi, x_hi, h_lo, x_lo]
        switch (seg) {
            case 0:  asrc = hin; acol = off; break;
            case 1:  asrc = xt;  acol = off; break;
            case 2:  asrc = hin; acol = 256 + off; break;
            default: asrc = xt;  acol = 256 + off; break;
        }
    } else {     // A segs: [h_hi, h_lo]
        asrc = hin; acol = (seg == 1 ? 256 : 0) + off;
    }
    const __half* bsrc = W + (size_t)kc * 64;
    const uint32_t Ab = sbase + stage * STAGEB;
    const uint32_t Bb = Ab + A_TILEB;
    // A: 64 rows x 8 x 16B = 512 transfers -> 2/thread
#pragma unroll
    for (int j = 0; j < 2; j++) {
        int idx = tid + j * 256;
        int row = idx >> 3, c8 = idx & 7;
        CPASYNC16(Ab + (uint32_t)(row * ROWB + c8 * 16),
                  (const void*)(asrc + (size_t)(m0 + row) * AKW + acol + c8 * 8));
    }
    // B: 128 rows x 8 x 16B = 1024 transfers -> 4/thread
#pragma unroll
    for (int j = 0; j < 4; j++) {
        int idx = tid + j * 256;
        int row = idx >> 3, c8 = idx & 7;
        CPASYNC16(Bb + (uint32_t)(row * ROWB + c8 * 16),
                  (const void*)(bsrc + (size_t)(n0 + row) * wstride + c8 * 8));
    }
}

// ---------------- fragment loads for one k16 slice ----------------
__device__ __forceinline__ void load_frags(int ks, uint32_t Ab, uint32_t Bb,
                                           uint32_t a_off, uint32_t b_off,
                                           uint32_t af[2][4], uint32_t bf[4][2]) {
#pragma unroll
    for (int mt = 0; mt < 2; mt++)
        LDSM4(af[mt][0], af[mt][1], af[mt][2], af[mt][3],
              Ab + a_off + mt * (16 * ROWB) + ks * 32);
#pragma unroll
    for (int p = 0; p < 2; p++) {
        uint32_t r0, r1, r2, r3;
        LDSM4(r0, r1, r2, r3, Bb + b_off + p * (16 * ROWB) + ks * 32);
        bf[2 * p][0] = r0; bf[2 * p][1] = r1;
        bf[2 * p + 1][0] = r2; bf[2 * p + 1][1] = r3;
    }
}

// ---------------- fused LSTM step: fp16 mma.sync, 64x128 tile, 2 CTA/SM ------------
__global__ __launch_bounds__(256, 2)
void step_mma(int ping, int t, float* __restrict__ outp, int ostride) {
    extern __shared__ char smem[];
    const int tid = threadIdx.x;
    const int wid = tid >> 5, lane = tid & 31;
    const int warp_m = wid >> 2, warp_n = wid & 3;   // 2 x 4 warp grid, warp = 32x32
    const int n0 = blockIdx.x * TN, m0 = blockIdx.y * TM;
    const int enc = (t >= 0);
    const int NCH = enc ? (KW_ENC / 64) : (KW_AR / 64);   // 16 or 8
    const __half* __restrict__ hin = g_hbuf[ping];
    __half* __restrict__ hout = g_hbuf[ping ^ 1];
    const __half* __restrict__ W = enc ? g_Wb : g_Wsb;
    const int wstride = enc ? KW_ENC : KW_AR;
    const __half* __restrict__ xt =
        enc ? (g_xs + (size_t)t * BB * AKW) : (const __half*)0;

    const uint32_t sbase = smem_u32(smem);

    const uint32_t a_off = (uint32_t)((warp_m * 32 + (lane & 7) + ((lane >> 3) & 1) * 8) * ROWB
                                      + ((lane >> 4) & 1) * 16);
    const uint32_t b_off = (uint32_t)((warp_n * 32 + (lane & 7) + ((lane >> 4) & 1) * 8) * ROWB
                                      + ((lane >> 3) & 1) * 16);

    float acc[2][4][4];
#pragma unroll
    for (int i = 0; i < 2; i++)
#pragma unroll
        for (int j = 0; j < 4; j++)
#pragma unroll
            for (int r = 0; r < 4; r++) acc[i][j][r] = 0.0f;

    // prologue: issue chunks 0, 1
    issue_chunk(0, 0, sbase, m0, n0, hin, xt, enc, W, wstride, tid);
    CP_COMMIT();
    issue_chunk(1, 1, sbase, m0, n0, hin, xt, enc, W, wstride, tid);
    CP_COMMIT();

    int st_cur = 0, st_nxt = 2;   // stage of chunk i, stage of chunk i+2
    for (int i = 0; i < NCH; i++) {
        CP_WAIT1();            // chunk i landed (only newest group may be in flight)
        __syncthreads();       // cross-thread visibility + stage-reuse safety

        const int nx = i + 2;
        if (nx < NCH)
            issue_chunk(nx, st_nxt, sbase, m0, n0, hin, xt, enc, W, wstride, tid);
        CP_COMMIT();           // commit every iter to keep group arithmetic fixed

        const uint32_t Ab = sbase + st_cur * STAGEB;
        const uint32_t Bb = Ab + A_TILEB;
        if (++st_cur == STAGES) st_cur = 0;
        if (++st_nxt == STAGES) st_nxt = 0;

        uint32_t af[2][2][4], bf[2][4][2];
        load_frags(0, Ab, Bb, a_off, b_off, af[0], bf[0]);
#pragma unroll
        for (int ks = 0; ks < 4; ks++) {
            const int cur = ks & 1;
            if (ks < 3)
                load_frags(ks + 1, Ab, Bb, a_off, b_off, af[cur ^ 1], bf[cur ^ 1]);
#pragma unroll
            for (int mt = 0; mt < 2; mt++)
#pragma unroll
                for (int nt = 0; nt < 4; nt++)
                    MMA16816(acc[mt][nt], af[cur][mt], bf[cur][nt]);
        }
    }

    // ---------------- fused epilogue: quad gather via shfl -> gates -> (h, c) ----------
    const int c = lane & 3, g = lane >> 2;
#pragma unroll
    for (int mt = 0; mt < 2; mt++)
#pragma unroll
        for (int nt = 0; nt < 4; nt++) {
            float q0 = acc[mt][nt][0], q1 = acc[mt][nt][1];
            float q2 = acc[mt][nt][2], q3 = acc[mt][nt][3];
            float p0 = __shfl_xor_sync(0xffffffffu, q0, 1);
            float p1 = __shfl_xor_sync(0xffffffffu, q1, 1);
            float p2 = __shfl_xor_sync(0xffffffffu, q2, 1);
            float p3 = __shfl_xor_sync(0xffffffffu, q3, 1);
            float gi, gf, gg, go;
            int row;
            if ((c & 1) == 0) { gi = q0; gf = q1; gg = p0; go = p1; row = g; }
            else              { gi = p2; gf = p3; gg = q2; go = q3; row = g + 8; }
            const int nq = n0 + warp_n * 32 + nt * 8 + (c >> 1) * 4;
            const int brow = m0 + warp_m * 32 + mt * 16 + row;
            const float4 bs = *(const float4*)&g_bias[nq];
            gi += bs.x; gf += bs.y; gg += bs.z; go += bs.w;
            const float iv = 1.0f / (1.0f + __expf(-gi));
            const float fv = 1.0f / (1.0f + __expf(-gf));
            const float gv = tanhf(gg);
            const float ov = 1.0f / (1.0f + __expf(-go));
            const int j = nq >> 2;
            const int ci = brow * HH + j;
            const float cn = fv * g_c[ci] + iv * gv;
            const float hn = ov * tanhf(cn);
            g_c[ci] = cn;
            __half hi = __float2half(hn);
            __half lo = __float2half(hn - __half2float(hi));
            hout[(size_t)brow * AKW + j] = hi;
            hout[(size_t)brow * AKW + 256 + j] = lo;
            if (outp) outp[(size_t)brow * ostride + j] = hn;
        }
}

// ---------------- host launcher (graph-capturable, alloc-free) ----------------
extern "C" void kernel_launch(void* const* d_in, const int* in_sizes, int n_in,
                              void* d_out, int out_size) {
    const float* x0  = (const float*)d_in[0];
    const float* Wih = (const float*)d_in[1];
    const float* Whh = (const float*)d_in[2];
    const float* bih = (const float*)d_in[3];
    const float* bhh = (const float*)d_in[4];
    float* out = (float*)d_out;

    const int n_steps = out_size / (BB * HH) - 1;
    const int ostride = (n_steps + 1) * HH;

    cudaFuncSetAttribute(step_mma, cudaFuncAttributeMaxDynamicSharedMemorySize, SM_TOT);

    init_k<<<512, 256>>>();
    prep_w<<<2048, 256>>>(Wih, Whh, bih, bhh);
    prep_x<<<4096, 256>>>(x0);

    dim3 grid(TN == 128 ? 8 : 16, BB / TM);   // 8 x 32 = 256 CTAs, 2/SM
    int p = 0;
    for (int t = 0; t < SS; t++) {
        float* op = (t == SS - 1) ? out : (float*)0;
        step_mma<<<grid, 256, SM_TOT>>>(p, t, op, ostride);
        p ^= 1;
    }
    for (int s = 0; s < n_steps; s++) {
        step_mma<<<grid, 256, SM_TOT>>>(p, -1, out + (size_t)(s + 1) * HH, ostride);
        p ^= 1;
    }
}